// round 3
// baseline (speedup 1.0000x reference)
#include <cuda_runtime.h>
#include <math.h>

// Problem constants
#define BSZ 1024
#define NN  7
#define DD  1024
#define BN  (BSZ*NN)   // 7168

// ---------------- scratch (device globals; no allocation allowed) ----------------
__device__ float g_q[BN*DD];
__device__ float g_k[BN*DD];
__device__ float g_v[BN*DD];
__device__ float g_la[BN*DD];
__device__ float g_rb[BN*DD];
__device__ float g_cc[BSZ*DD];
__device__ float g_msg[BN*DD];
__device__ float g_h1[BN*DD];
__device__ float g_i1[BN*DD];
__device__ float g_implogit[BN];
__device__ float g_pedge[BSZ];
__device__ float g_pnon[BSZ];
__device__ float g_palign[BSZ];

__constant__ int c_adj[49] = {
    1,1,0,0,1,1,1,
    1,1,1,1,1,1,1,
    0,1,1,0,1,0,1,
    0,1,0,1,1,1,1,
    1,1,1,1,1,1,1,
    1,1,0,1,1,1,1,
    1,1,1,1,1,1,1
};

__device__ __forceinline__ float gelu_f(float x) {
    // exact GELU: x * Phi(x)
    return x * normcdff(x);
}

// ---------------- generic fp32 SGEMM, 128x128x8 tile, 8x8 per thread ----------------
// C[r, c] = sum_k A(r,k) * W[k, c] (+bias) (+resid) (optional gelu)
// A(r,k): k <  KA : A  + r*lda + k
//         k >= KA : A2 + rowmap(r)*1024 + (k-KA);  rowmap = identity or (r/7)*7+6
__global__ void __launch_bounds__(256) sgemm128(
    const float* __restrict__ A, int lda,
    const float* __restrict__ A2, int a2map, int KA, int K,
    const float* __restrict__ W, int ldw,
    const float* __restrict__ bias,
    const float* __restrict__ resid,
    float* __restrict__ C, int ldc,
    int dogelu)
{
    __shared__ float As[8][128];
    __shared__ float Bs[8][128];
    const int tid = threadIdx.x;
    const int tx = tid & 15;
    const int ty = tid >> 4;
    const long row0 = (long)blockIdx.y * 128;
    const int  col0 = blockIdx.x * 128;

    const int arow = tid >> 1;
    const int ak   = (tid & 1) * 4;
    const int bk   = tid >> 5;
    const int bcol = (tid & 31) * 4;

    float acc[8][8];
#pragma unroll
    for (int i = 0; i < 8; i++)
#pragma unroll
        for (int j = 0; j < 8; j++) acc[i][j] = 0.f;

    for (int k0 = 0; k0 < K; k0 += 8) {
        float4 av;
        {
            int  kg = k0 + ak;
            long r  = row0 + arow;
            if (kg < KA) {
                av = *(const float4*)(A + r * (long)lda + kg);
            } else {
                long rr = a2map ? (r / 7) * 7 + 6 : r;
                av = *(const float4*)(A2 + rr * 1024 + (kg - KA));
            }
        }
        float4 bv = *(const float4*)(W + (long)(k0 + bk) * ldw + (col0 + bcol));
        __syncthreads();
        As[ak + 0][arow] = av.x;
        As[ak + 1][arow] = av.y;
        As[ak + 2][arow] = av.z;
        As[ak + 3][arow] = av.w;
        *(float4*)&Bs[bk][bcol] = bv;
        __syncthreads();
#pragma unroll
        for (int kk = 0; kk < 8; kk++) {
            float4 a0 = *(const float4*)&As[kk][ty * 4];
            float4 a1 = *(const float4*)&As[kk][64 + ty * 4];
            float4 b0 = *(const float4*)&Bs[kk][tx * 4];
            float4 b1 = *(const float4*)&Bs[kk][64 + tx * 4];
            float aa[8] = {a0.x, a0.y, a0.z, a0.w, a1.x, a1.y, a1.z, a1.w};
            float bb[8] = {b0.x, b0.y, b0.z, b0.w, b1.x, b1.y, b1.z, b1.w};
#pragma unroll
            for (int i = 0; i < 8; i++)
#pragma unroll
                for (int j = 0; j < 8; j++)
                    acc[i][j] = fmaf(aa[i], bb[j], acc[i][j]);
        }
    }

#pragma unroll
    for (int ih = 0; ih < 2; ih++)
#pragma unroll
        for (int ii = 0; ii < 4; ii++) {
            long r = row0 + ih * 64 + ty * 4 + ii;
            int  i = ih * 4 + ii;
#pragma unroll
            for (int jh = 0; jh < 2; jh++) {
                int c = col0 + jh * 64 + tx * 4;
                float4 v;
                v.x = acc[i][jh * 4 + 0];
                v.y = acc[i][jh * 4 + 1];
                v.z = acc[i][jh * 4 + 2];
                v.w = acc[i][jh * 4 + 3];
                if (bias) {
                    v.x += bias[c + 0]; v.y += bias[c + 1];
                    v.z += bias[c + 2]; v.w += bias[c + 3];
                }
                if (resid) {
                    float4 rv = *(const float4*)(resid + r * (long)ldc + c);
                    v.x += rv.x; v.y += rv.y; v.z += rv.z; v.w += rv.w;
                }
                if (dogelu) {
                    v.x = gelu_f(v.x); v.y = gelu_f(v.y);
                    v.z = gelu_f(v.z); v.w = gelu_f(v.w);
                }
                *(float4*)(C + r * (long)ldc + c) = v;
            }
        }
}

// ---------------- per-batch attention + edge MLP + softmax + messages ----------------
__global__ void __launch_bounds__(256) attn_edge_kernel(
    const float* __restrict__ q, const float* __restrict__ k, const float* __restrict__ v,
    const float* __restrict__ la, const float* __restrict__ rb, const float* __restrict__ cc,
    const float* __restrict__ be1, const float* __restrict__ We2, const float* __restrict__ be2,
    float* __restrict__ attn_out, float* __restrict__ msg)
{
    const int b = blockIdx.x;
    const int tid = threadIdx.x;
    const int warp = tid >> 5, lane = tid & 31;
    __shared__ float sRB[7][1024];
    __shared__ float sW2[1024];
    __shared__ float sP[7][7];

    for (int idx = tid; idx < 7 * 1024; idx += 256) {
        int m = idx >> 10, d = idx & 1023;
        sRB[m][d] = rb[((long)b * 7 + m) * 1024 + d] + cc[(long)b * 1024 + d] + be1[d];
    }
    for (int d = tid; d < 1024; d += 256) sW2[d] = We2[d];
    __syncthreads();

    for (int p = warp; p < 49; p += 8) {
        int n = p / 7, m = p % 7;
        const float* qp  = q  + ((long)b * 7 + n) * 1024;
        const float* kp  = k  + ((long)b * 7 + m) * 1024;
        const float* lap = la + ((long)b * 7 + n) * 1024;
        float s = 0.f, e = 0.f;
        for (int d = lane; d < 1024; d += 32) {
            s = fmaf(qp[d], kp[d], s);
            float x = lap[d] + sRB[m][d];
            e = fmaf(gelu_f(x), sW2[d], e);
        }
#pragma unroll
        for (int o = 16; o > 0; o >>= 1) {
            s += __shfl_xor_sync(0xffffffffu, s, o);
            e += __shfl_xor_sync(0xffffffffu, e, o);
        }
        if (lane == 0) {
            float mask = c_adj[p] ? 0.f : -10000.f;
            sP[n][m] = s * (1.f / 32.f) + e + be2[0] + mask;
        }
    }
    __syncthreads();
    if (tid < 7) {
        int n = tid;
        float mx = -1e30f;
        for (int m = 0; m < 7; m++) mx = fmaxf(mx, sP[n][m]);
        float pv[7], sum = 0.f;
        for (int m = 0; m < 7; m++) { pv[m] = expf(sP[n][m] - mx); sum += pv[m]; }
        float inv = 1.f / sum;
        for (int m = 0; m < 7; m++) {
            float a = pv[m] * inv;
            sP[n][m] = a;
            attn_out[(long)b * 49 + n * 7 + m] = a;
        }
    }
    __syncthreads();
    for (int idx = tid; idx < 7 * 1024; idx += 256) {
        int n = idx >> 10, d = idx & 1023;
        float s = 0.f;
#pragma unroll
        for (int m = 0; m < 7; m++)
            s = fmaf(sP[n][m], v[((long)b * 7 + m) * 1024 + d], s);
        msg[((long)b * 7 + n) * 1024 + d] = s;
    }
}

// ---------------- importance logits: row-dot with Wi2 ----------------
__global__ void __launch_bounds__(256) imp_logit_kernel(
    const float* __restrict__ i1, const float* __restrict__ Wi2,
    const float* __restrict__ bi2, float* __restrict__ out)
{
    int row  = blockIdx.x * 8 + (threadIdx.x >> 5);
    int lane = threadIdx.x & 31;
    const float* p = i1 + (long)row * 1024;
    float s = 0.f;
    for (int d = lane; d < 1024; d += 32) s = fmaf(p[d], Wi2[d], s);
#pragma unroll
    for (int o = 16; o > 0; o >>= 1) s += __shfl_xor_sync(0xffffffffu, s, o);
    if (lane == 0) out[row] = s + bi2[0];
}

// ---------------- per-batch finalize: softmax+cap, fused, loss partials ----------------
__global__ void __launch_bounds__(256) finalize_kernel(
    const float* __restrict__ upd, const float* __restrict__ implogit,
    float* __restrict__ out_fused, float* __restrict__ out_imp)
{
    const int b = blockIdx.x;
    const int tid = threadIdx.x;
    const int warp = tid >> 5, lane = tid & 31;
    __shared__ float sU[7][1024];
    __shared__ float sF[1024];
    __shared__ float simp[7];
    __shared__ float sdot[7][7];
    __shared__ float sal[7];
    __shared__ float sff;

    for (int idx = tid; idx < 7 * 1024; idx += 256)
        sU[idx >> 10][idx & 1023] = upd[(long)b * 7168 + idx];

    if (tid == 0) {
        const float capv[7]  = {1.f, 1.f, 1.f, 0.26f, 1.f, 1.f, 0.24f};
        const float freev[7] = {1.f, 1.f, 1.f, 0.f,   1.f, 1.f, 0.f};
        float l[7], mx = -1e30f;
        for (int n = 0; n < 7; n++) { l[n] = implogit[b * 7 + n]; mx = fmaxf(mx, l[n]); }
        float sum = 0.f;
        for (int n = 0; n < 7; n++) { l[n] = expf(l[n] - mx); sum += l[n]; }
        float imp[7];
        for (int n = 0; n < 7; n++) imp[n] = l[n] / sum;
        float capped[7], fm = 0.f, cs = 0.f;
        for (int n = 0; n < 7; n++) {
            capped[n] = fminf(imp[n], capv[n]);
            fm += imp[n] * freev[n];
            cs += capped[n];
        }
        float residual = fmaxf(1.f - cs, 0.f);
        float redis[7], tot = 0.f;
        for (int n = 0; n < 7; n++) {
            float share = (fm > 1e-6f) ? (imp[n] * freev[n] / fmaxf(fm, 1e-6f))
                                       : (freev[n] / 5.f);
            redis[n] = capped[n] + share * residual;
            tot += redis[n];
        }
        float invt = 1.f / fmaxf(tot, 1e-6f);
        for (int n = 0; n < 7; n++) {
            float r = redis[n] * invt;
            simp[n] = r;
            out_imp[b * 7 + n] = r;
        }
    }
    __syncthreads();

    for (int d = tid; d < 1024; d += 256) {
        float f = 0.f;
#pragma unroll
        for (int n = 0; n < 7; n++) f = fmaf(simp[n], sU[n][d], f);
        sF[d] = f;
        out_fused[(long)b * 1024 + d] = f;
    }
    __syncthreads();

    // 36 dot jobs: 28 pair dots (n<=m), 7 align dots, 1 ||fused||^2
    for (int p = warp; p < 36; p += 8) {
        const float *x, *y;
        int n = 0, m = 0;
        if (p < 28) {
            int t = p;
            while (t >= 7 - n) { t -= 7 - n; n++; }
            m = n + t;
            x = sU[n]; y = sU[m];
        } else if (p < 35) {
            n = p - 28; x = sU[n]; y = sF;
        } else {
            x = sF; y = sF;
        }
        float s = 0.f;
        for (int d = lane; d < 1024; d += 32) s = fmaf(x[d], y[d], s);
#pragma unroll
        for (int o = 16; o > 0; o >>= 1) s += __shfl_xor_sync(0xffffffffu, s, o);
        if (lane == 0) {
            if (p < 28)      { sdot[n][m] = s; sdot[m][n] = s; }
            else if (p < 35) { sal[n] = s; }
            else             { sff = s; }
        }
    }
    __syncthreads();

    if (tid == 0) {
        float nrm[7];
        for (int n = 0; n < 7; n++) nrm[n] = sqrtf(sdot[n][n]);
        float nf = sqrtf(sff);
        float edge = 0.f, non = 0.f, al = 0.f;
        for (int n = 0; n < 7; n++) {
            for (int m = 0; m < 7; m++) {
                float cosv = sdot[n][m] / fmaxf(nrm[n] * nrm[m], 1e-8f);
                if (c_adj[n * 7 + m]) edge += 1.f - cosv;
                else                  non  += fmaxf(cosv - 0.35f, 0.f);
            }
            al += 1.f - sal[n] / (fmaxf(nrm[n], 1e-12f) * fmaxf(nf, 1e-12f));
        }
        g_pedge[b] = edge;
        g_pnon[b]  = non;
        g_palign[b] = al;
    }
}

// ---------------- deterministic loss reduction ----------------
__global__ void __launch_bounds__(256) loss_kernel(float* __restrict__ out_phys,
                                                   float* __restrict__ out_align)
{
    __shared__ float se[256], sn[256], sa[256];
    int tid = threadIdx.x;
    float e = 0.f, n = 0.f, a = 0.f;
    for (int b = tid; b < BSZ; b += 256) { e += g_pedge[b]; n += g_pnon[b]; a += g_palign[b]; }
    se[tid] = e; sn[tid] = n; sa[tid] = a;
    __syncthreads();
    for (int o = 128; o > 0; o >>= 1) {
        if (tid < o) { se[tid] += se[tid + o]; sn[tid] += sn[tid + o]; sa[tid] += sa[tid + o]; }
        __syncthreads();
    }
    if (tid == 0) {
        float phys  = se[0] / 41.f + 0.5f * (sn[0] / 8.f);
        float align = sa[0] / (1024.f * 7.f);
        out_phys[0]  = phys;   // output 5 = phys + 0.0*align
        out_align[0] = align;
    }
}

// ---------------- launch ----------------
extern "C" void kernel_launch(void* const* d_in, const int* in_sizes, int n_in,
                              void* d_out, int out_size)
{
    const float* nodes = (const float*)d_in[0];
    const float* Wq  = (const float*)d_in[1];
    const float* bq  = (const float*)d_in[2];
    const float* Wk  = (const float*)d_in[3];
    const float* bk  = (const float*)d_in[4];
    const float* Wv  = (const float*)d_in[5];
    const float* bv  = (const float*)d_in[6];
    const float* We1 = (const float*)d_in[7];
    const float* be1 = (const float*)d_in[8];
    const float* We2 = (const float*)d_in[9];
    const float* be2 = (const float*)d_in[10];
    const float* Wu1 = (const float*)d_in[11];
    const float* bu1 = (const float*)d_in[12];
    const float* Wu2 = (const float*)d_in[13];
    const float* bu2 = (const float*)d_in[14];
    const float* Wi1 = (const float*)d_in[15];
    const float* bi1 = (const float*)d_in[16];
    const float* Wi2 = (const float*)d_in[17];
    const float* bi2 = (const float*)d_in[18];

    float* out = (float*)d_out;
    const long OFF_FUSED = 0;
    const long OFF_UPD   = 1024L * 1024;                 // 1,048,576
    const long OFF_IMP   = OFF_UPD + 7168L * 1024;       // 8,388,608
    const long OFF_ATTN  = OFF_IMP + 7168;               // 8,395,776
    const long OFF_PHYS  = OFF_ATTN + 1024L * 49;        // 8,445,952
    const long OFF_ALIGN = OFF_PHYS + 1;                 // 8,445,953

    float *pq, *pk, *pv, *pla, *prb, *pcc, *pmsg, *ph1, *pi1, *pil;
    cudaGetSymbolAddress((void**)&pq,  g_q);
    cudaGetSymbolAddress((void**)&pk,  g_k);
    cudaGetSymbolAddress((void**)&pv,  g_v);
    cudaGetSymbolAddress((void**)&pla, g_la);
    cudaGetSymbolAddress((void**)&prb, g_rb);
    cudaGetSymbolAddress((void**)&pcc, g_cc);
    cudaGetSymbolAddress((void**)&pmsg, g_msg);
    cudaGetSymbolAddress((void**)&ph1, g_h1);
    cudaGetSymbolAddress((void**)&pi1, g_i1);
    cudaGetSymbolAddress((void**)&pil, g_implogit);

    dim3 blk(256);
    dim3 gBig(8, 56);   // 1024/128 cols, 7168/128 rows
    dim3 gCc(8, 8);     // 1024/128 rows

    // q, k, v, la, rb
    sgemm128<<<gBig, blk>>>(nodes, 1024, nullptr, 0, 1024, 1024, Wq, 1024, bq, nullptr, pq, 1024, 0);
    sgemm128<<<gBig, blk>>>(nodes, 1024, nullptr, 0, 1024, 1024, Wk, 1024, bk, nullptr, pk, 1024, 0);
    sgemm128<<<gBig, blk>>>(nodes, 1024, nullptr, 0, 1024, 1024, Wv, 1024, bv, nullptr, pv, 1024, 0);
    sgemm128<<<gBig, blk>>>(nodes, 1024, nullptr, 0, 1024, 1024, We1,               1024, nullptr, nullptr, pla, 1024, 0);
    sgemm128<<<gBig, blk>>>(nodes, 1024, nullptr, 0, 1024, 1024, We1 + 1024 * 1024, 1024, nullptr, nullptr, prb, 1024, 0);
    // cc = nodes[:, -1] @ Wc : rows stride 7*1024, base offset 6*1024
    sgemm128<<<gCc, blk>>>(nodes + 6 * 1024, 7 * 1024, nullptr, 0, 1024, 1024,
                           We1 + 2 * 1024 * 1024, 1024, nullptr, nullptr, pcc, 1024, 0);

    attn_edge_kernel<<<1024, blk>>>(pq, pk, pv, pla, prb, pcc, be1, We2, be2,
                                    out + OFF_ATTN, pmsg);

    // h1 = gelu([nodes, msg] @ Wu1 + bu1)
    sgemm128<<<gBig, blk>>>(nodes, 1024, pmsg, 0, 1024, 2048, Wu1, 1024, bu1, nullptr, ph1, 1024, 1);
    // updated = h1 @ Wu2 + bu2 + nodes   (written straight to output)
    sgemm128<<<gBig, blk>>>(ph1, 1024, nullptr, 0, 1024, 1024, Wu2, 1024, bu2, nodes, out + OFF_UPD, 1024, 0);
    // i1 = gelu([updated, gq] @ Wi1 + bi1); gq row = (r/7)*7+6
    sgemm128<<<gBig, blk>>>(out + OFF_UPD, 1024, out + OFF_UPD, 1, 1024, 2048, Wi1, 1024, bi1, nullptr, pi1, 1024, 1);

    imp_logit_kernel<<<896, blk>>>(pi1, Wi2, bi2, pil);
    finalize_kernel<<<1024, blk>>>(out + OFF_UPD, pil, out + OFF_FUSED, out + OFF_IMP);
    loss_kernel<<<1, blk>>>(out + OFF_PHYS, out + OFF_ALIGN);
}

// round 4
// speedup vs baseline: 1.3470x; 1.3470x over previous
#include <cuda_runtime.h>
#include <math.h>

// Problem constants
#define BSZ 1024
#define NN  7
#define DD  1024
#define BN  (BSZ*NN)   // 7168

typedef unsigned long long u64;

// ---------------- scratch (device globals; no allocation allowed) ----------------
__device__ float g_q[BN*DD];
__device__ float g_k[BN*DD];
__device__ float g_v[BN*DD];
__device__ float g_la[BN*DD];
__device__ float g_rb[BN*DD];
__device__ float g_cc[BSZ*DD];
__device__ float g_msg[BN*DD];
__device__ float g_h1[BN*DD];
__device__ float g_i1[BN*DD];
__device__ float g_implogit[BN];
__device__ float g_pedge[BSZ];
__device__ float g_pnon[BSZ];
__device__ float g_palign[BSZ];

__constant__ int c_adj[49] = {
    1,1,0,0,1,1,1,
    1,1,1,1,1,1,1,
    0,1,1,0,1,0,1,
    0,1,0,1,1,1,1,
    1,1,1,1,1,1,1,
    1,1,0,1,1,1,1,
    1,1,1,1,1,1,1
};

__device__ __forceinline__ float gelu_f(float x) {
    // exact GELU: x * Phi(x)
    return x * normcdff(x);
}

// ---------------- packed f32x2 helpers (sm_100+ FFMA2 path) ----------------
__device__ __forceinline__ u64 pack_dup(float x) {
    u64 r;
    asm("mov.b64 %0, {%1, %1};" : "=l"(r) : "f"(x));
    return r;
}
__device__ __forceinline__ void unpack2(u64 v, float& lo, float& hi) {
    asm("mov.b64 {%0, %1}, %2;" : "=f"(lo), "=f"(hi) : "l"(v));
}
__device__ __forceinline__ u64 fma2(u64 a, u64 b, u64 c) {
    u64 d;
    asm("fma.rn.f32x2 %0, %1, %2, %3;" : "=l"(d) : "l"(a), "l"(b), "l"(c));
    return d;
}

// ---------------- generic fp32 SGEMM, 128x128x8 tile, 8x8 per thread ----------------
// Inner product runs on the packed f32x2 FMA pipe (2x fp32 rate on sm_103a).
// C[r, c] = sum_k A(r,k) * W[k, c] (+bias) (+resid) (optional gelu)
// A(r,k): k <  KA : A  + r*lda + k
//         k >= KA : A2 + rowmap(r)*1024 + (k-KA);  rowmap = identity or (r/7)*7+6
__global__ void __launch_bounds__(256) sgemm128(
    const float* __restrict__ A, int lda,
    const float* __restrict__ A2, int a2map, int KA, int K,
    const float* __restrict__ W, int ldw,
    const float* __restrict__ bias,
    const float* __restrict__ resid,
    float* __restrict__ C, int ldc,
    int dogelu)
{
    __shared__ __align__(16) float As[8][128];
    __shared__ __align__(16) float Bs[8][128];
    const int tid = threadIdx.x;
    const int tx = tid & 15;
    const int ty = tid >> 4;
    const long row0 = (long)blockIdx.y * 128;
    const int  col0 = blockIdx.x * 128;

    const int arow = tid >> 1;
    const int ak   = (tid & 1) * 4;
    const int bk   = tid >> 5;
    const int bcol = (tid & 31) * 4;

    // accumulators: 8 rows x 4 column-pairs of packed f32x2
    u64 acc[8][4];
#pragma unroll
    for (int i = 0; i < 8; i++)
#pragma unroll
        for (int j = 0; j < 4; j++) acc[i][j] = 0ull;   // bit pattern {0.f, 0.f}

    for (int k0 = 0; k0 < K; k0 += 8) {
        float4 av;
        {
            int  kg = k0 + ak;
            long r  = row0 + arow;
            if (kg < KA) {
                av = *(const float4*)(A + r * (long)lda + kg);
            } else {
                long rr = a2map ? (r / 7) * 7 + 6 : r;
                av = *(const float4*)(A2 + rr * 1024 + (kg - KA));
            }
        }
        float4 bv = *(const float4*)(W + (long)(k0 + bk) * ldw + (col0 + bcol));
        __syncthreads();
        As[ak + 0][arow] = av.x;
        As[ak + 1][arow] = av.y;
        As[ak + 2][arow] = av.z;
        As[ak + 3][arow] = av.w;
        *(float4*)&Bs[bk][bcol] = bv;
        __syncthreads();
#pragma unroll
        for (int kk = 0; kk < 8; kk++) {
            float4 a0 = *(const float4*)&As[kk][ty * 4];
            float4 a1 = *(const float4*)&As[kk][64 + ty * 4];
            // B column-pairs, loaded directly as 64-bit (16B-aligned offsets)
            const u64* pb0 = (const u64*)&Bs[kk][tx * 4];
            const u64* pb1 = (const u64*)&Bs[kk][64 + tx * 4];
            u64 b[4];
            b[0] = pb0[0]; b[1] = pb0[1];
            b[2] = pb1[0]; b[3] = pb1[1];
            float aa[8] = {a0.x, a0.y, a0.z, a0.w, a1.x, a1.y, a1.z, a1.w};
#pragma unroll
            for (int i = 0; i < 8; i++) {
                u64 ad = pack_dup(aa[i]);
#pragma unroll
                for (int j = 0; j < 4; j++)
                    acc[i][j] = fma2(ad, b[j], acc[i][j]);
            }
        }
    }

#pragma unroll
    for (int ih = 0; ih < 2; ih++)
#pragma unroll
        for (int ii = 0; ii < 4; ii++) {
            long r = row0 + ih * 64 + ty * 4 + ii;
            int  i = ih * 4 + ii;
#pragma unroll
            for (int jh = 0; jh < 2; jh++) {
                int c = col0 + jh * 64 + tx * 4;
                float4 v;
                unpack2(acc[i][jh * 2 + 0], v.x, v.y);
                unpack2(acc[i][jh * 2 + 1], v.z, v.w);
                if (bias) {
                    v.x += bias[c + 0]; v.y += bias[c + 1];
                    v.z += bias[c + 2]; v.w += bias[c + 3];
                }
                if (resid) {
                    float4 rv = *(const float4*)(resid + r * (long)ldc + c);
                    v.x += rv.x; v.y += rv.y; v.z += rv.z; v.w += rv.w;
                }
                if (dogelu) {
                    v.x = gelu_f(v.x); v.y = gelu_f(v.y);
                    v.z = gelu_f(v.z); v.w = gelu_f(v.w);
                }
                *(float4*)(C + r * (long)ldc + c) = v;
            }
        }
}

// ---------------- per-batch attention + edge MLP + softmax + messages ----------------
__global__ void __launch_bounds__(256) attn_edge_kernel(
    const float* __restrict__ q, const float* __restrict__ k, const float* __restrict__ v,
    const float* __restrict__ la, const float* __restrict__ rb, const float* __restrict__ cc,
    const float* __restrict__ be1, const float* __restrict__ We2, const float* __restrict__ be2,
    float* __restrict__ attn_out, float* __restrict__ msg)
{
    const int b = blockIdx.x;
    const int tid = threadIdx.x;
    const int warp = tid >> 5, lane = tid & 31;
    __shared__ float sRB[7][1024];
    __shared__ float sW2[1024];
    __shared__ float sP[7][7];

    for (int idx = tid; idx < 7 * 1024; idx += 256) {
        int m = idx >> 10, d = idx & 1023;
        sRB[m][d] = rb[((long)b * 7 + m) * 1024 + d] + cc[(long)b * 1024 + d] + be1[d];
    }
    for (int d = tid; d < 1024; d += 256) sW2[d] = We2[d];
    __syncthreads();

    for (int p = warp; p < 49; p += 8) {
        int n = p / 7, m = p % 7;
        const float* qp  = q  + ((long)b * 7 + n) * 1024;
        const float* kp  = k  + ((long)b * 7 + m) * 1024;
        const float* lap = la + ((long)b * 7 + n) * 1024;
        float s = 0.f, e = 0.f;
        for (int d = lane; d < 1024; d += 32) {
            s = fmaf(qp[d], kp[d], s);
            float x = lap[d] + sRB[m][d];
            e = fmaf(gelu_f(x), sW2[d], e);
        }
#pragma unroll
        for (int o = 16; o > 0; o >>= 1) {
            s += __shfl_xor_sync(0xffffffffu, s, o);
            e += __shfl_xor_sync(0xffffffffu, e, o);
        }
        if (lane == 0) {
            float mask = c_adj[p] ? 0.f : -10000.f;
            sP[n][m] = s * (1.f / 32.f) + e + be2[0] + mask;
        }
    }
    __syncthreads();
    if (tid < 7) {
        int n = tid;
        float mx = -1e30f;
        for (int m = 0; m < 7; m++) mx = fmaxf(mx, sP[n][m]);
        float pv[7], sum = 0.f;
        for (int m = 0; m < 7; m++) { pv[m] = expf(sP[n][m] - mx); sum += pv[m]; }
        float inv = 1.f / sum;
        for (int m = 0; m < 7; m++) {
            float a = pv[m] * inv;
            sP[n][m] = a;
            attn_out[(long)b * 49 + n * 7 + m] = a;
        }
    }
    __syncthreads();
    for (int idx = tid; idx < 7 * 1024; idx += 256) {
        int n = idx >> 10, d = idx & 1023;
        float s = 0.f;
#pragma unroll
        for (int m = 0; m < 7; m++)
            s = fmaf(sP[n][m], v[((long)b * 7 + m) * 1024 + d], s);
        msg[((long)b * 7 + n) * 1024 + d] = s;
    }
}

// ---------------- importance logits: row-dot with Wi2 ----------------
__global__ void __launch_bounds__(256) imp_logit_kernel(
    const float* __restrict__ i1, const float* __restrict__ Wi2,
    const float* __restrict__ bi2, float* __restrict__ out)
{
    int row  = blockIdx.x * 8 + (threadIdx.x >> 5);
    int lane = threadIdx.x & 31;
    const float* p = i1 + (long)row * 1024;
    float s = 0.f;
    for (int d = lane; d < 1024; d += 32) s = fmaf(p[d], Wi2[d], s);
#pragma unroll
    for (int o = 16; o > 0; o >>= 1) s += __shfl_xor_sync(0xffffffffu, s, o);
    if (lane == 0) out[row] = s + bi2[0];
}

// ---------------- per-batch finalize: softmax+cap, fused, loss partials ----------------
__global__ void __launch_bounds__(256) finalize_kernel(
    const float* __restrict__ upd, const float* __restrict__ implogit,
    float* __restrict__ out_fused, float* __restrict__ out_imp)
{
    const int b = blockIdx.x;
    const int tid = threadIdx.x;
    const int warp = tid >> 5, lane = tid & 31;
    __shared__ float sU[7][1024];
    __shared__ float sF[1024];
    __shared__ float simp[7];
    __shared__ float sdot[7][7];
    __shared__ float sal[7];
    __shared__ float sff;

    for (int idx = tid; idx < 7 * 1024; idx += 256)
        sU[idx >> 10][idx & 1023] = upd[(long)b * 7168 + idx];

    if (tid == 0) {
        const float capv[7]  = {1.f, 1.f, 1.f, 0.26f, 1.f, 1.f, 0.24f};
        const float freev[7] = {1.f, 1.f, 1.f, 0.f,   1.f, 1.f, 0.f};
        float l[7], mx = -1e30f;
        for (int n = 0; n < 7; n++) { l[n] = implogit[b * 7 + n]; mx = fmaxf(mx, l[n]); }
        float sum = 0.f;
        for (int n = 0; n < 7; n++) { l[n] = expf(l[n] - mx); sum += l[n]; }
        float imp[7];
        for (int n = 0; n < 7; n++) imp[n] = l[n] / sum;
        float capped[7], fm = 0.f, cs = 0.f;
        for (int n = 0; n < 7; n++) {
            capped[n] = fminf(imp[n], capv[n]);
            fm += imp[n] * freev[n];
            cs += capped[n];
        }
        float residual = fmaxf(1.f - cs, 0.f);
        float redis[7], tot = 0.f;
        for (int n = 0; n < 7; n++) {
            float share = (fm > 1e-6f) ? (imp[n] * freev[n] / fmaxf(fm, 1e-6f))
                                       : (freev[n] / 5.f);
            redis[n] = capped[n] + share * residual;
            tot += redis[n];
        }
        float invt = 1.f / fmaxf(tot, 1e-6f);
        for (int n = 0; n < 7; n++) {
            float r = redis[n] * invt;
            simp[n] = r;
            out_imp[b * 7 + n] = r;
        }
    }
    __syncthreads();

    for (int d = tid; d < 1024; d += 256) {
        float f = 0.f;
#pragma unroll
        for (int n = 0; n < 7; n++) f = fmaf(simp[n], sU[n][d], f);
        sF[d] = f;
        out_fused[(long)b * 1024 + d] = f;
    }
    __syncthreads();

    // 36 dot jobs: 28 pair dots (n<=m), 7 align dots, 1 ||fused||^2
    for (int p = warp; p < 36; p += 8) {
        const float *x, *y;
        int n = 0, m = 0;
        if (p < 28) {
            int t = p;
            while (t >= 7 - n) { t -= 7 - n; n++; }
            m = n + t;
            x = sU[n]; y = sU[m];
        } else if (p < 35) {
            n = p - 28; x = sU[n]; y = sF;
        } else {
            x = sF; y = sF;
        }
        float s = 0.f;
        for (int d = lane; d < 1024; d += 32) s = fmaf(x[d], y[d], s);
#pragma unroll
        for (int o = 16; o > 0; o >>= 1) s += __shfl_xor_sync(0xffffffffu, s, o);
        if (lane == 0) {
            if (p < 28)      { sdot[n][m] = s; sdot[m][n] = s; }
            else if (p < 35) { sal[n] = s; }
            else             { sff = s; }
        }
    }
    __syncthreads();

    if (tid == 0) {
        float nrm[7];
        for (int n = 0; n < 7; n++) nrm[n] = sqrtf(sdot[n][n]);
        float nf = sqrtf(sff);
        float edge = 0.f, non = 0.f, al = 0.f;
        for (int n = 0; n < 7; n++) {
            for (int m = 0; m < 7; m++) {
                float cosv = sdot[n][m] / fmaxf(nrm[n] * nrm[m], 1e-8f);
                if (c_adj[n * 7 + m]) edge += 1.f - cosv;
                else                  non  += fmaxf(cosv - 0.35f, 0.f);
            }
            al += 1.f - sal[n] / (fmaxf(nrm[n], 1e-12f) * fmaxf(nf, 1e-12f));
        }
        g_pedge[b] = edge;
        g_pnon[b]  = non;
        g_palign[b] = al;
    }
}

// ---------------- deterministic loss reduction ----------------
__global__ void __launch_bounds__(256) loss_kernel(float* __restrict__ out_phys,
                                                   float* __restrict__ out_align)
{
    __shared__ float se[256], sn[256], sa[256];
    int tid = threadIdx.x;
    float e = 0.f, n = 0.f, a = 0.f;
    for (int b = tid; b < BSZ; b += 256) { e += g_pedge[b]; n += g_pnon[b]; a += g_palign[b]; }
    se[tid] = e; sn[tid] = n; sa[tid] = a;
    __syncthreads();
    for (int o = 128; o > 0; o >>= 1) {
        if (tid < o) { se[tid] += se[tid + o]; sn[tid] += sn[tid + o]; sa[tid] += sa[tid + o]; }
        __syncthreads();
    }
    if (tid == 0) {
        float phys  = se[0] / 41.f + 0.5f * (sn[0] / 8.f);
        float align = sa[0] / (1024.f * 7.f);
        out_phys[0]  = phys;   // output 5 = phys + 0.0*align
        out_align[0] = align;
    }
}

// ---------------- launch ----------------
extern "C" void kernel_launch(void* const* d_in, const int* in_sizes, int n_in,
                              void* d_out, int out_size)
{
    const float* nodes = (const float*)d_in[0];
    const float* Wq  = (const float*)d_in[1];
    const float* bq  = (const float*)d_in[2];
    const float* Wk  = (const float*)d_in[3];
    const float* bk  = (const float*)d_in[4];
    const float* Wv  = (const float*)d_in[5];
    const float* bv  = (const float*)d_in[6];
    const float* We1 = (const float*)d_in[7];
    const float* be1 = (const float*)d_in[8];
    const float* We2 = (const float*)d_in[9];
    const float* be2 = (const float*)d_in[10];
    const float* Wu1 = (const float*)d_in[11];
    const float* bu1 = (const float*)d_in[12];
    const float* Wu2 = (const float*)d_in[13];
    const float* bu2 = (const float*)d_in[14];
    const float* Wi1 = (const float*)d_in[15];
    const float* bi1 = (const float*)d_in[16];
    const float* Wi2 = (const float*)d_in[17];
    const float* bi2 = (const float*)d_in[18];

    float* out = (float*)d_out;
    const long OFF_FUSED = 0;
    const long OFF_UPD   = 1024L * 1024;                 // 1,048,576
    const long OFF_IMP   = OFF_UPD + 7168L * 1024;       // 8,388,608
    const long OFF_ATTN  = OFF_IMP + 7168;               // 8,395,776
    const long OFF_PHYS  = OFF_ATTN + 1024L * 49;        // 8,445,952
    const long OFF_ALIGN = OFF_PHYS + 1;                 // 8,445,953

    float *pq, *pk, *pv, *pla, *prb, *pcc, *pmsg, *ph1, *pi1, *pil;
    cudaGetSymbolAddress((void**)&pq,  g_q);
    cudaGetSymbolAddress((void**)&pk,  g_k);
    cudaGetSymbolAddress((void**)&pv,  g_v);
    cudaGetSymbolAddress((void**)&pla, g_la);
    cudaGetSymbolAddress((void**)&prb, g_rb);
    cudaGetSymbolAddress((void**)&pcc, g_cc);
    cudaGetSymbolAddress((void**)&pmsg, g_msg);
    cudaGetSymbolAddress((void**)&ph1, g_h1);
    cudaGetSymbolAddress((void**)&pi1, g_i1);
    cudaGetSymbolAddress((void**)&pil, g_implogit);

    dim3 blk(256);
    dim3 gBig(8, 56);   // 1024/128 cols, 7168/128 rows
    dim3 gCc(8, 8);     // 1024/128 rows

    // q, k, v, la, rb
    sgemm128<<<gBig, blk>>>(nodes, 1024, nullptr, 0, 1024, 1024, Wq, 1024, bq, nullptr, pq, 1024, 0);
    sgemm128<<<gBig, blk>>>(nodes, 1024, nullptr, 0, 1024, 1024, Wk, 1024, bk, nullptr, pk, 1024, 0);
    sgemm128<<<gBig, blk>>>(nodes, 1024, nullptr, 0, 1024, 1024, Wv, 1024, bv, nullptr, pv, 1024, 0);
    sgemm128<<<gBig, blk>>>(nodes, 1024, nullptr, 0, 1024, 1024, We1,               1024, nullptr, nullptr, pla, 1024, 0);
    sgemm128<<<gBig, blk>>>(nodes, 1024, nullptr, 0, 1024, 1024, We1 + 1024 * 1024, 1024, nullptr, nullptr, prb, 1024, 0);
    // cc = nodes[:, -1] @ Wc : rows stride 7*1024, base offset 6*1024
    sgemm128<<<gCc, blk>>>(nodes + 6 * 1024, 7 * 1024, nullptr, 0, 1024, 1024,
                           We1 + 2 * 1024 * 1024, 1024, nullptr, nullptr, pcc, 1024, 0);

    attn_edge_kernel<<<1024, blk>>>(pq, pk, pv, pla, prb, pcc, be1, We2, be2,
                                    out + OFF_ATTN, pmsg);

    // h1 = gelu([nodes, msg] @ Wu1 + bu1)
    sgemm128<<<gBig, blk>>>(nodes, 1024, pmsg, 0, 1024, 2048, Wu1, 1024, bu1, nullptr, ph1, 1024, 1);
    // updated = h1 @ Wu2 + bu2 + nodes   (written straight to output)
    sgemm128<<<gBig, blk>>>(ph1, 1024, nullptr, 0, 1024, 1024, Wu2, 1024, bu2, nodes, out + OFF_UPD, 1024, 0);
    // i1 = gelu([updated, gq] @ Wi1 + bi1); gq row = (r/7)*7+6
    sgemm128<<<gBig, blk>>>(out + OFF_UPD, 1024, out + OFF_UPD, 1, 1024, 2048, Wi1, 1024, bi1, nullptr, pi1, 1024, 1);

    imp_logit_kernel<<<896, blk>>>(pi1, Wi2, bi2, pil);
    finalize_kernel<<<1024, blk>>>(out + OFF_UPD, pil, out + OFF_FUSED, out + OFF_IMP);
    loss_kernel<<<1, blk>>>(out + OFF_PHYS, out + OFF_ALIGN);
}

// round 6
// speedup vs baseline: 3.0871x; 2.2918x over previous
#include <cuda_runtime.h>
#include <cuda_bf16.h>
#include <math.h>

// Problem constants
#define BSZ 1024
#define NN  7
#define DD  1024
#define BN  (BSZ*NN)   // 7168

typedef unsigned short ushort_t;

// ---------------- fp32 scratch ----------------
__device__ float g_q[BN*DD];
__device__ float g_k[BN*DD];
__device__ float g_v[BN*DD];
__device__ float g_la[BN*DD];
__device__ float g_rb[BN*DD];
__device__ float g_cc[BSZ*DD];
__device__ float g_msg[BN*DD];
__device__ float g_i1[BN*DD];
__device__ float g_implogit[BN];
__device__ float g_pedge[BSZ];
__device__ float g_pnon[BSZ];
__device__ float g_palign[BSZ];

// ---------------- bf16 (ushort) scratch ----------------
__device__ ushort_t g_cat1h[BN*2048], g_cat1l[BN*2048];   // [nodes | msg]
__device__ ushort_t g_h1h[BN*DD],     g_h1l[BN*DD];       // gelu hidden
__device__ ushort_t g_cat2h[BN*2048], g_cat2l[BN*2048];   // [updated | gq]
// transposed weights, [N, K] K-major
__device__ ushort_t g_wqh[DD*DD],  g_wql[DD*DD];
__device__ ushort_t g_wkh[DD*DD],  g_wkl[DD*DD];
__device__ ushort_t g_wvh[DD*DD],  g_wvl[DD*DD];
__device__ ushort_t g_wah[DD*DD],  g_wal[DD*DD];
__device__ ushort_t g_wbh[DD*DD],  g_wbl[DD*DD];
__device__ ushort_t g_wch[DD*DD],  g_wcl[DD*DD];
__device__ ushort_t g_wu1h[DD*2048], g_wu1l[DD*2048];
__device__ ushort_t g_wu2h[DD*DD],   g_wu2l[DD*DD];
__device__ ushort_t g_wi1h[DD*2048], g_wi1l[DD*2048];

__constant__ int c_adj[49] = {
    1,1,0,0,1,1,1,
    1,1,1,1,1,1,1,
    0,1,1,0,1,0,1,
    0,1,0,1,1,1,1,
    1,1,1,1,1,1,1,
    1,1,0,1,1,1,1,
    1,1,1,1,1,1,1
};

__device__ __forceinline__ float gelu_f(float x) { return x * normcdff(x); }

// ---------------- helpers ----------------
__device__ __forceinline__ unsigned smem_u32(const void* p) {
    unsigned a;
    asm("{ .reg .u64 t; cvta.to.shared.u64 t, %1; cvt.u32.u64 %0, t; }" : "=r"(a) : "l"(p));
    return a;
}
#define SMEM_SWIZZLE_128B(x) ((x) ^ (((x) >> 3) & 0x70))

#define CP_ASYNC16(s, g) \
    asm volatile("cp.async.cg.shared.global [%0], [%1], 16;" :: "r"(s), "l"(g) : "memory")
#define CP_COMMIT() asm volatile("cp.async.commit_group;" ::: "memory")
#define CP_WAIT0()  asm volatile("cp.async.wait_group 0;" ::: "memory")

#define LDSM4(r, a) \
    asm volatile("ldmatrix.sync.aligned.m8n8.x4.shared.b16 {%0,%1,%2,%3}, [%4];" \
        : "=r"((r)[0]), "=r"((r)[1]), "=r"((r)[2]), "=r"((r)[3]) : "r"(a))

#define MMA16816(d, a, b) \
    asm volatile("mma.sync.aligned.m16n8k16.row.col.f32.bf16.bf16.f32 " \
        "{%0,%1,%2,%3}, {%4,%5,%6,%7}, {%8,%9}, {%0,%1,%2,%3};" \
        : "+f"((d)[0]), "+f"((d)[1]), "+f"((d)[2]), "+f"((d)[3]) \
        : "r"((a)[0]), "r"((a)[1]), "r"((a)[2]), "r"((a)[3]), "r"((b)[0]), "r"((b)[1]))

// ---------------- bf16 split ----------------
__device__ __forceinline__ void split_bf16(float v, ushort_t& h, ushort_t& l) {
    __nv_bfloat16 hb = __float2bfloat16(v);
    __nv_bfloat16 lb = __float2bfloat16(v - __bfloat162float(hb));
    h = *reinterpret_cast<ushort_t*>(&hb);
    l = *reinterpret_cast<ushort_t*>(&lb);
}

// ---------------- weight transpose+split: W[K,N] -> Wt[N,K] hi/lo bf16 ----------------
__global__ void __launch_bounds__(256) transpose_split(
    const float* __restrict__ W, int K, int N,
    ushort_t* __restrict__ th, ushort_t* __restrict__ tl)
{
    __shared__ float t[32][33];
    int n0 = blockIdx.x * 32, k0 = blockIdx.y * 32;
    int tx = threadIdx.x & 31, ty = threadIdx.x >> 5;
#pragma unroll
    for (int i = 0; i < 32; i += 8)
        t[ty + i][tx] = W[(long)(k0 + ty + i) * N + n0 + tx];
    __syncthreads();
#pragma unroll
    for (int i = 0; i < 32; i += 8) {
        float v = t[tx][ty + i];
        long o = (long)(n0 + ty + i) * K + k0 + tx;
        ushort_t h, l; split_bf16(v, h, l);
        th[o] = h; tl[o] = l;
    }
}

// ---------------- activation convert: fp32 [M,1024] -> hi/lo at col offset ----------------
__global__ void __launch_bounds__(256) conv_split(
    const float* __restrict__ src,
    ushort_t* __restrict__ dh, ushort_t* __restrict__ dl,
    int dld, int dcol0)
{
    long idx = (long)blockIdx.x * 256 + threadIdx.x;
    int r = (int)(idx >> 10), d = (int)(idx & 1023);
    float v = src[idx];
    ushort_t h, l; split_bf16(v, h, l);
    long o = (long)r * dld + dcol0 + d;
    dh[o] = h; dl[o] = l;
}

// ---------------- gather gq half of cat2 ----------------
__global__ void __launch_bounds__(256) gather_gq()
{
    long idx = (long)blockIdx.x * 256 + threadIdx.x;   // over BN*1024
    int r = (int)(idx >> 10), d = (int)(idx & 1023);
    int g = (r / 7) * 7 + 6;
    g_cat2h[(long)r * 2048 + 1024 + d] = g_cat2h[(long)g * 2048 + d];
    g_cat2l[(long)r * 2048 + 1024 + d] = g_cat2l[(long)g * 2048 + d];
}

// ---------------- HMMA split-bf16 GEMM: C = A @ Wt^T ----------------
// Tiles: CTA 128x128, 8 warps of 64x32, K-chunk 64, cp.async double buffer.
#define TILE_B   16384                      // 128 rows x 128 bytes (64 bf16)
#define STAGE_B  (4*TILE_B)                 // Ah, Al, Bh, Bl
#define HMMA_SMEM (2*STAGE_B)               // 131072

__device__ __forceinline__ void load_tile_async(
    unsigned dst, const ushort_t* __restrict__ src, long ld, long r0, int kc)
{
    int t = threadIdx.x;
    int rr = t >> 3;            // 0..31
    int o  = (t & 7) << 4;      // byte offset within 128B row
#pragma unroll
    for (int p = 0; p < 4; p++) {
        int r = rr + p * 32;
        const void* g = (const void*)(src + (r0 + r) * ld + kc + (o >> 1));
        unsigned s = dst + SMEM_SWIZZLE_128B(r * 128 + o);
        CP_ASYNC16(s, g);
    }
}

__global__ void __launch_bounds__(256) hmma_gemm(
    const ushort_t* __restrict__ a_h, const ushort_t* __restrict__ a_l, long lda,
    const ushort_t* __restrict__ b_h, const ushort_t* __restrict__ b_l, long ldb,
    int K,
    const float* __restrict__ bias,
    const float* __restrict__ resid,
    float* __restrict__ C,
    ushort_t* __restrict__ o_h, ushort_t* __restrict__ o_l, int ldo,
    int dogelu)
{
    extern __shared__ char smem[];
    unsigned sb = smem_u32(smem);
    const int tid = threadIdx.x;
    const int wid = tid >> 5, lane = tid & 31;
    const int wm = wid & 1, wn = wid >> 1;    // warp tile: rows wm*64, cols wn*32
    const long row0 = (long)blockIdx.y * 128;
    const int  col0 = blockIdx.x * 128;
    const int NCH = K >> 6;

    float acc[4][4][4];
#pragma unroll
    for (int i = 0; i < 4; i++)
#pragma unroll
        for (int j = 0; j < 4; j++)
#pragma unroll
            for (int e = 0; e < 4; e++) acc[i][j][e] = 0.f;

    // precomputed ldmatrix per-lane offsets (pre-swizzle)
    const int aRow  = wm * 64 + (lane & 15);
    const int aKoff = (lane >> 4) << 4;
    const int bRow0 = wn * 32 + (lane & 7) + ((lane >> 4) << 3);
    const int bKoff = ((lane >> 3) & 1) << 4;

    // prologue: chunk 0 -> stage 0
    {
        unsigned s0 = sb;
        load_tile_async(s0 + 0 * TILE_B, a_h, lda, row0, 0);
        load_tile_async(s0 + 1 * TILE_B, a_l, lda, row0, 0);
        load_tile_async(s0 + 2 * TILE_B, b_h, ldb, col0, 0);
        load_tile_async(s0 + 3 * TILE_B, b_l, ldb, col0, 0);
        CP_COMMIT();
        CP_WAIT0();
    }
    __syncthreads();

    for (int c = 0; c < NCH; c++) {
        int s = c & 1;
        // issue next chunk's loads first (overlap with MMA)
        if (c + 1 < NCH) {
            unsigned sn = sb + (s ^ 1) * STAGE_B;
            int kc = (c + 1) << 6;
            load_tile_async(sn + 0 * TILE_B, a_h, lda, row0, kc);
            load_tile_async(sn + 1 * TILE_B, a_l, lda, row0, kc);
            load_tile_async(sn + 2 * TILE_B, b_h, ldb, col0, kc);
            load_tile_async(sn + 3 * TILE_B, b_l, ldb, col0, kc);
            CP_COMMIT();
        }
        unsigned stage = sb + s * STAGE_B;
#pragma unroll
        for (int k16 = 0; k16 < 4; k16++) {
            unsigned ah[4][4], al[4][4];
#pragma unroll
            for (int mt = 0; mt < 4; mt++) {
                unsigned off = (unsigned)((aRow + mt * 16) * 128 + k16 * 32 + aKoff);
                off = SMEM_SWIZZLE_128B(off);
                LDSM4(ah[mt], stage + 0 * TILE_B + off);
                LDSM4(al[mt], stage + 1 * TILE_B + off);
            }
            unsigned bhf[4][2], blf[4][2];
#pragma unroll
            for (int np = 0; np < 2; np++) {
                unsigned off = (unsigned)((bRow0 + np * 16) * 128 + k16 * 32 + bKoff);
                off = SMEM_SWIZZLE_128B(off);
                unsigned r[4];
                LDSM4(r, stage + 2 * TILE_B + off);
                bhf[2*np][0] = r[0]; bhf[2*np][1] = r[1];
                bhf[2*np+1][0] = r[2]; bhf[2*np+1][1] = r[3];
                LDSM4(r, stage + 3 * TILE_B + off);
                blf[2*np][0] = r[0]; blf[2*np][1] = r[1];
                blf[2*np+1][0] = r[2]; blf[2*np+1][1] = r[3];
            }
#pragma unroll
            for (int mt = 0; mt < 4; mt++)
#pragma unroll
                for (int nt = 0; nt < 4; nt++) {
                    MMA16816(acc[mt][nt], ah[mt], bhf[nt]);
                    MMA16816(acc[mt][nt], ah[mt], blf[nt]);
                    MMA16816(acc[mt][nt], al[mt], bhf[nt]);
                }
        }
        if (c + 1 < NCH) CP_WAIT0();
        __syncthreads();
    }

    // epilogue: thread t holds rows wm*64+mt*16+(lane>>2)+{0,8}, cols wn*32+nt*8+(lane&3)*2+{0,1}
#pragma unroll
    for (int mt = 0; mt < 4; mt++)
#pragma unroll
        for (int h = 0; h < 2; h++) {
            long r = row0 + wm * 64 + mt * 16 + (lane >> 2) + h * 8;
#pragma unroll
            for (int nt = 0; nt < 4; nt++)
#pragma unroll
                for (int e = 0; e < 2; e++) {
                    int col = col0 + wn * 32 + nt * 8 + (lane & 3) * 2 + e;
                    float v = acc[mt][nt][h * 2 + e];
                    if (bias)  v += bias[col];
                    if (resid) v += resid[r * 1024 + col];
                    if (dogelu) v = gelu_f(v);
                    if (C) C[r * 1024 + col] = v;
                    if (o_h) {
                        ushort_t hh, ll; split_bf16(v, hh, ll);
                        o_h[r * (long)ldo + col] = hh;
                        o_l[r * (long)ldo + col] = ll;
                    }
                }
        }
}

// ---------------- per-batch attention + edge MLP + softmax + messages ----------------
__global__ void __launch_bounds__(256) attn_edge_kernel(
    const float* __restrict__ q, const float* __restrict__ k, const float* __restrict__ v,
    const float* __restrict__ la, const float* __restrict__ rb, const float* __restrict__ cc,
    const float* __restrict__ be1, const float* __restrict__ We2, const float* __restrict__ be2,
    float* __restrict__ attn_out, float* __restrict__ msg)
{
    const int b = blockIdx.x;
    const int tid = threadIdx.x;
    const int warp = tid >> 5, lane = tid & 31;
    __shared__ float sRB[7][1024];
    __shared__ float sW2[1024];
    __shared__ float sP[7][7];

    for (int idx = tid; idx < 7 * 1024; idx += 256) {
        int m = idx >> 10, d = idx & 1023;
        sRB[m][d] = rb[((long)b * 7 + m) * 1024 + d] + cc[(long)b * 1024 + d] + be1[d];
    }
    for (int d = tid; d < 1024; d += 256) sW2[d] = We2[d];
    __syncthreads();

    for (int p = warp; p < 49; p += 8) {
        int n = p / 7, m = p % 7;
        const float* qp  = q  + ((long)b * 7 + n) * 1024;
        const float* kp  = k  + ((long)b * 7 + m) * 1024;
        const float* lap = la + ((long)b * 7 + n) * 1024;
        float s = 0.f, e = 0.f;
        for (int d = lane; d < 1024; d += 32) {
            s = fmaf(qp[d], kp[d], s);
            float x = lap[d] + sRB[m][d];
            e = fmaf(gelu_f(x), sW2[d], e);
        }
#pragma unroll
        for (int o = 16; o > 0; o >>= 1) {
            s += __shfl_xor_sync(0xffffffffu, s, o);
            e += __shfl_xor_sync(0xffffffffu, e, o);
        }
        if (lane == 0) {
            float mask = c_adj[p] ? 0.f : -10000.f;
            sP[n][m] = s * (1.f / 32.f) + e + be2[0] + mask;
        }
    }
    __syncthreads();
    if (tid < 7) {
        int n = tid;
        float mx = -1e30f;
        for (int m = 0; m < 7; m++) mx = fmaxf(mx, sP[n][m]);
        float pv[7], sum = 0.f;
        for (int m = 0; m < 7; m++) { pv[m] = expf(sP[n][m] - mx); sum += pv[m]; }
        float inv = 1.f / sum;
        for (int m = 0; m < 7; m++) {
            float a = pv[m] * inv;
            sP[n][m] = a;
            attn_out[(long)b * 49 + n * 7 + m] = a;
        }
    }
    __syncthreads();
    for (int idx = tid; idx < 7 * 1024; idx += 256) {
        int n = idx >> 10, d = idx & 1023;
        float s = 0.f;
#pragma unroll
        for (int m = 0; m < 7; m++)
            s = fmaf(sP[n][m], v[((long)b * 7 + m) * 1024 + d], s);
        msg[((long)b * 7 + n) * 1024 + d] = s;
    }
}

// ---------------- importance logits ----------------
__global__ void __launch_bounds__(256) imp_logit_kernel(
    const float* __restrict__ i1, const float* __restrict__ Wi2,
    const float* __restrict__ bi2, float* __restrict__ out)
{
    int row  = blockIdx.x * 8 + (threadIdx.x >> 5);
    int lane = threadIdx.x & 31;
    const float* p = i1 + (long)row * 1024;
    float s = 0.f;
    for (int d = lane; d < 1024; d += 32) s = fmaf(p[d], Wi2[d], s);
#pragma unroll
    for (int o = 16; o > 0; o >>= 1) s += __shfl_xor_sync(0xffffffffu, s, o);
    if (lane == 0) out[row] = s + bi2[0];
}

// ---------------- per-batch finalize ----------------
__global__ void __launch_bounds__(256) finalize_kernel(
    const float* __restrict__ upd, const float* __restrict__ implogit,
    float* __restrict__ out_fused, float* __restrict__ out_imp)
{
    const int b = blockIdx.x;
    const int tid = threadIdx.x;
    const int warp = tid >> 5, lane = tid & 31;
    __shared__ float sU[7][1024];
    __shared__ float sF[1024];
    __shared__ float simp[7];
    __shared__ float sdot[7][7];
    __shared__ float sal[7];
    __shared__ float sff;

    for (int idx = tid; idx < 7 * 1024; idx += 256)
        sU[idx >> 10][idx & 1023] = upd[(long)b * 7168 + idx];

    if (tid == 0) {
        const float capv[7]  = {1.f, 1.f, 1.f, 0.26f, 1.f, 1.f, 0.24f};
        const float freev[7] = {1.f, 1.f, 1.f, 0.f,   1.f, 1.f, 0.f};
        float l[7], mx = -1e30f;
        for (int n = 0; n < 7; n++) { l[n] = implogit[b * 7 + n]; mx = fmaxf(mx, l[n]); }
        float sum = 0.f;
        for (int n = 0; n < 7; n++) { l[n] = expf(l[n] - mx); sum += l[n]; }
        float imp[7];
        for (int n = 0; n < 7; n++) imp[n] = l[n] / sum;
        float capped[7], fm = 0.f, cs = 0.f;
        for (int n = 0; n < 7; n++) {
            capped[n] = fminf(imp[n], capv[n]);
            fm += imp[n] * freev[n];
            cs += capped[n];
        }
        float residual = fmaxf(1.f - cs, 0.f);
        float redis[7], tot = 0.f;
        for (int n = 0; n < 7; n++) {
            float share = (fm > 1e-6f) ? (imp[n] * freev[n] / fmaxf(fm, 1e-6f))
                                       : (freev[n] / 5.f);
            redis[n] = capped[n] + share * residual;
            tot += redis[n];
        }
        float invt = 1.f / fmaxf(tot, 1e-6f);
        for (int n = 0; n < 7; n++) {
            float r = redis[n] * invt;
            simp[n] = r;
            out_imp[b * 7 + n] = r;
        }
    }
    __syncthreads();

    for (int d = tid; d < 1024; d += 256) {
        float f = 0.f;
#pragma unroll
        for (int n = 0; n < 7; n++) f = fmaf(simp[n], sU[n][d], f);
        sF[d] = f;
        out_fused[(long)b * 1024 + d] = f;
    }
    __syncthreads();

    for (int p = warp; p < 36; p += 8) {
        const float *x, *y;
        int n = 0, m = 0;
        if (p < 28) {
            int t = p;
            while (t >= 7 - n) { t -= 7 - n; n++; }
            m = n + t;
            x = sU[n]; y = sU[m];
        } else if (p < 35) {
            n = p - 28; x = sU[n]; y = sF;
        } else {
            x = sF; y = sF;
        }
        float s = 0.f;
        for (int d = lane; d < 1024; d += 32) s = fmaf(x[d], y[d], s);
#pragma unroll
        for (int o = 16; o > 0; o >>= 1) s += __shfl_xor_sync(0xffffffffu, s, o);
        if (lane == 0) {
            if (p < 28)      { sdot[n][m] = s; sdot[m][n] = s; }
            else if (p < 35) { sal[n] = s; }
            else             { sff = s; }
        }
    }
    __syncthreads();

    if (tid == 0) {
        float nrm[7];
        for (int n = 0; n < 7; n++) nrm[n] = sqrtf(sdot[n][n]);
        float nf = sqrtf(sff);
        float edge = 0.f, non = 0.f, al = 0.f;
        for (int n = 0; n < 7; n++) {
            for (int m = 0; m < 7; m++) {
                float cosv = sdot[n][m] / fmaxf(nrm[n] * nrm[m], 1e-8f);
                if (c_adj[n * 7 + m]) edge += 1.f - cosv;
                else                  non  += fmaxf(cosv - 0.35f, 0.f);
            }
            al += 1.f - sal[n] / (fmaxf(nrm[n], 1e-12f) * fmaxf(nf, 1e-12f));
        }
        g_pedge[b] = edge;
        g_pnon[b]  = non;
        g_palign[b] = al;
    }
}

// ---------------- deterministic loss reduction ----------------
__global__ void __launch_bounds__(256) loss_kernel(float* __restrict__ out_phys,
                                                   float* __restrict__ out_align)
{
    __shared__ float se[256], sn[256], sa[256];
    int tid = threadIdx.x;
    float e = 0.f, n = 0.f, a = 0.f;
    for (int b = tid; b < BSZ; b += 256) { e += g_pedge[b]; n += g_pnon[b]; a += g_palign[b]; }
    se[tid] = e; sn[tid] = n; sa[tid] = a;
    __syncthreads();
    for (int o = 128; o > 0; o >>= 1) {
        if (tid < o) { se[tid] += se[tid + o]; sn[tid] += sn[tid + o]; sa[tid] += sa[tid + o]; }
        __syncthreads();
    }
    if (tid == 0) {
        out_phys[0]  = se[0] / 41.f + 0.5f * (sn[0] / 8.f);
        out_align[0] = sa[0] / (1024.f * 7.f);
    }
}

// ---------------- launch ----------------
extern "C" void kernel_launch(void* const* d_in, const int* in_sizes, int n_in,
                              void* d_out, int out_size)
{
    const float* nodes = (const float*)d_in[0];
    const float* Wq  = (const float*)d_in[1];
    const float* bq  = (const float*)d_in[2];
    const float* Wk  = (const float*)d_in[3];
    const float* bk  = (const float*)d_in[4];
    const float* Wv  = (const float*)d_in[5];
    const float* bv  = (const float*)d_in[6];
    const float* We1 = (const float*)d_in[7];
    const float* be1 = (const float*)d_in[8];
    const float* We2 = (const float*)d_in[9];
    const float* be2 = (const float*)d_in[10];
    const float* Wu1 = (const float*)d_in[11];
    const float* bu1 = (const float*)d_in[12];
    const float* Wu2 = (const float*)d_in[13];
    const float* bu2 = (const float*)d_in[14];
    const float* Wi1 = (const float*)d_in[15];
    const float* bi1 = (const float*)d_in[16];
    const float* Wi2 = (const float*)d_in[17];
    const float* bi2 = (const float*)d_in[18];

    float* out = (float*)d_out;
    const long OFF_FUSED = 0;
    const long OFF_UPD   = 1024L * 1024;
    const long OFF_IMP   = OFF_UPD + 7168L * 1024;
    const long OFF_ATTN  = OFF_IMP + 7168;
    const long OFF_PHYS  = OFF_ATTN + 1024L * 49;
    const long OFF_ALIGN = OFF_PHYS + 1;

    float *pq, *pk, *pv, *pla, *prb, *pcc, *pmsg, *pi1, *pil;
    cudaGetSymbolAddress((void**)&pq,  g_q);
    cudaGetSymbolAddress((void**)&pk,  g_k);
    cudaGetSymbolAddress((void**)&pv,  g_v);
    cudaGetSymbolAddress((void**)&pla, g_la);
    cudaGetSymbolAddress((void**)&prb, g_rb);
    cudaGetSymbolAddress((void**)&pcc, g_cc);
    cudaGetSymbolAddress((void**)&pmsg, g_msg);
    cudaGetSymbolAddress((void**)&pi1, g_i1);
    cudaGetSymbolAddress((void**)&pil, g_implogit);

    ushort_t *cat1h, *cat1l, *h1h, *h1l, *cat2h, *cat2l;
    ushort_t *wqh, *wql, *wkh, *wkl, *wvh, *wvl, *wah, *wal, *wbh, *wbl, *wch, *wcl;
    ushort_t *wu1h, *wu1l, *wu2h, *wu2l, *wi1h, *wi1l;
    cudaGetSymbolAddress((void**)&cat1h, g_cat1h);
    cudaGetSymbolAddress((void**)&cat1l, g_cat1l);
    cudaGetSymbolAddress((void**)&h1h,   g_h1h);
    cudaGetSymbolAddress((void**)&h1l,   g_h1l);
    cudaGetSymbolAddress((void**)&cat2h, g_cat2h);
    cudaGetSymbolAddress((void**)&cat2l, g_cat2l);
    cudaGetSymbolAddress((void**)&wqh, g_wqh);  cudaGetSymbolAddress((void**)&wql, g_wql);
    cudaGetSymbolAddress((void**)&wkh, g_wkh);  cudaGetSymbolAddress((void**)&wkl, g_wkl);
    cudaGetSymbolAddress((void**)&wvh, g_wvh);  cudaGetSymbolAddress((void**)&wvl, g_wvl);
    cudaGetSymbolAddress((void**)&wah, g_wah);  cudaGetSymbolAddress((void**)&wal, g_wal);
    cudaGetSymbolAddress((void**)&wbh, g_wbh);  cudaGetSymbolAddress((void**)&wbl, g_wbl);
    cudaGetSymbolAddress((void**)&wch, g_wch);  cudaGetSymbolAddress((void**)&wcl, g_wcl);
    cudaGetSymbolAddress((void**)&wu1h, g_wu1h); cudaGetSymbolAddress((void**)&wu1l, g_wu1l);
    cudaGetSymbolAddress((void**)&wu2h, g_wu2h); cudaGetSymbolAddress((void**)&wu2l, g_wu2l);
    cudaGetSymbolAddress((void**)&wi1h, g_wi1h); cudaGetSymbolAddress((void**)&wi1l, g_wi1l);

    cudaFuncSetAttribute(hmma_gemm, cudaFuncAttributeMaxDynamicSharedMemorySize, HMMA_SMEM);

    dim3 blk(256);
    dim3 gT1(32, 32);   // transpose K=1024
    dim3 gT2(32, 64);   // transpose K=2048
    dim3 gBig(8, 56);   // 128x128 tiles over [7168, 1024]
    dim3 gCc(8, 8);     // [1024, 1024]
    int  convBlocks = (int)((7168L * 1024) / 256);   // 28672

    // weight transposes + splits
    transpose_split<<<gT1, blk>>>(Wq, 1024, 1024, wqh, wql);
    transpose_split<<<gT1, blk>>>(Wk, 1024, 1024, wkh, wkl);
    transpose_split<<<gT1, blk>>>(Wv, 1024, 1024, wvh, wvl);
    transpose_split<<<gT1, blk>>>(We1,                 1024, 1024, wah, wal);
    transpose_split<<<gT1, blk>>>(We1 + 1024 * 1024,   1024, 1024, wbh, wbl);
    transpose_split<<<gT1, blk>>>(We1 + 2 * 1024 * 1024, 1024, 1024, wch, wcl);
    transpose_split<<<gT2, blk>>>(Wu1, 2048, 1024, wu1h, wu1l);
    transpose_split<<<gT1, blk>>>(Wu2, 1024, 1024, wu2h, wu2l);
    transpose_split<<<gT2, blk>>>(Wi1, 2048, 1024, wi1h, wi1l);

    // nodes -> cat1[:, 0:1024]
    conv_split<<<convBlocks, blk>>>(nodes, cat1h, cat1l, 2048, 0);

    // q,k,v,la,rb
    hmma_gemm<<<gBig, blk, HMMA_SMEM>>>(cat1h, cat1l, 2048, wqh, wql, 1024, 1024, bq, nullptr, pq,  nullptr, nullptr, 0, 0);
    hmma_gemm<<<gBig, blk, HMMA_SMEM>>>(cat1h, cat1l, 2048, wkh, wkl, 1024, 1024, bk, nullptr, pk,  nullptr, nullptr, 0, 0);
    hmma_gemm<<<gBig, blk, HMMA_SMEM>>>(cat1h, cat1l, 2048, wvh, wvl, 1024, 1024, bv, nullptr, pv,  nullptr, nullptr, 0, 0);
    hmma_gemm<<<gBig, blk, HMMA_SMEM>>>(cat1h, cat1l, 2048, wah, wal, 1024, 1024, nullptr, nullptr, pla, nullptr, nullptr, 0, 0);
    hmma_gemm<<<gBig, blk, HMMA_SMEM>>>(cat1h, cat1l, 2048, wbh, wbl, 1024, 1024, nullptr, nullptr, prb, nullptr, nullptr, 0, 0);
    // cc: rows (i*7+6) of cat1 first half
    hmma_gemm<<<gCc, blk, HMMA_SMEM>>>(cat1h + 6 * 2048, cat1l + 6 * 2048, 7 * 2048,
                                       wch, wcl, 1024, 1024, nullptr, nullptr, pcc, nullptr, nullptr, 0, 0);

    attn_edge_kernel<<<1024, blk>>>(pq, pk, pv, pla, prb, pcc, be1, We2, be2,
                                    out + OFF_ATTN, pmsg);

    // msg -> cat1[:, 1024:2048]
    conv_split<<<convBlocks, blk>>>(pmsg, cat1h, cat1l, 2048, 1024);

    // h1 = gelu(cat1 @ Wu1 + bu1) -> bf16 only
    hmma_gemm<<<gBig, blk, HMMA_SMEM>>>(cat1h, cat1l, 2048, wu1h, wu1l, 2048, 2048, bu1, nullptr, nullptr, h1h, h1l, 1024, 1);
    // updated = h1 @ Wu2 + bu2 + nodes -> fp32 out + bf16 into cat2 first half
    hmma_gemm<<<gBig, blk, HMMA_SMEM>>>(h1h, h1l, 1024, wu2h, wu2l, 1024, 1024, bu2, nodes, out + OFF_UPD, cat2h, cat2l, 2048, 0);
    // fill gq half of cat2
    gather_gq<<<convBlocks, blk>>>();
    // i1 = gelu(cat2 @ Wi1 + bi1)
    hmma_gemm<<<gBig, blk, HMMA_SMEM>>>(cat2h, cat2l, 2048, wi1h, wi1l, 2048, 2048, bi1, nullptr, pi1, nullptr, nullptr, 0, 1);

    imp_logit_kernel<<<896, blk>>>(pi1, Wi2, bi2, pil);
    finalize_kernel<<<1024, blk>>>(out + OFF_UPD, pil, out + OFF_FUSED, out + OFF_IMP);
    loss_kernel<<<1, blk>>>(out + OFF_PHYS, out + OFF_ALIGN);
}

// round 7
// speedup vs baseline: 3.1014x; 1.0046x over previous
#include <cuda_runtime.h>
#include <cuda_bf16.h>
#include <math.h>

// Problem constants
#define BSZ 1024
#define NN  7
#define DD  1024
#define BN  (BSZ*NN)   // 7168

typedef unsigned short ushort_t;

// ---------------- fp32 scratch ----------------
__device__ float g_qkv[BN*5120];     // [q|k|v|la|rb]
__device__ float g_cc[BSZ*DD];
__device__ float g_i1[BN*DD];
__device__ float g_implogit[BN];
__device__ float g_pedge[BSZ];
__device__ float g_pnon[BSZ];
__device__ float g_palign[BSZ];
__device__ float g_bias5[5120];

// ---------------- bf16 (ushort) split scratch, all ld=1024 ----------------
__device__ ushort_t g_xh[BN*DD],  g_xl[BN*DD];    // nodes
__device__ ushort_t g_mh[BN*DD],  g_ml[BN*DD];    // messages
__device__ ushort_t g_uh[BN*DD],  g_ul[BN*DD];    // updated
__device__ ushort_t g_h1h[BN*DD], g_h1l[BN*DD];   // gelu hidden
// transposed weights, [N, K] K-major
__device__ ushort_t g_w5h[5120*DD], g_w5l[5120*DD];   // [Wq|Wk|Wv|Wa|Wb]
__device__ ushort_t g_wch[DD*DD],   g_wcl[DD*DD];
__device__ ushort_t g_wu1h[DD*2048], g_wu1l[DD*2048];
__device__ ushort_t g_wu2h[DD*DD],   g_wu2l[DD*DD];
__device__ ushort_t g_wi1h[DD*2048], g_wi1l[DD*2048];

__constant__ int c_adj[49] = {
    1,1,0,0,1,1,1,
    1,1,1,1,1,1,1,
    0,1,1,0,1,0,1,
    0,1,0,1,1,1,1,
    1,1,1,1,1,1,1,
    1,1,0,1,1,1,1,
    1,1,1,1,1,1,1
};
// list of unmasked (n,m) pairs, packed n*7+m (41 entries = ADJ.sum())
__constant__ unsigned char c_pairs[41] = {
    0,1,4,5,6,
    7,8,9,10,11,12,13,
    15,16,18,20,
    22,24,25,26,27,
    28,29,30,31,32,33,34,
    35,36,38,39,40,41,
    42,43,44,45,46,47,48
};

__device__ __forceinline__ float gelu_f(float x) { return x * normcdff(x); }

// ---------------- helpers ----------------
__device__ __forceinline__ unsigned smem_u32(const void* p) {
    unsigned a;
    asm("{ .reg .u64 t; cvta.to.shared.u64 t, %1; cvt.u32.u64 %0, t; }" : "=r"(a) : "l"(p));
    return a;
}
#define SMEM_SWIZZLE_128B(x) ((x) ^ (((x) >> 3) & 0x70))

#define CP_ASYNC16(s, g) \
    asm volatile("cp.async.cg.shared.global [%0], [%1], 16;" :: "r"(s), "l"(g) : "memory")
#define CP_COMMIT() asm volatile("cp.async.commit_group;" ::: "memory")
#define CP_WAIT0()  asm volatile("cp.async.wait_group 0;" ::: "memory")

#define LDSM4(r, a) \
    asm volatile("ldmatrix.sync.aligned.m8n8.x4.shared.b16 {%0,%1,%2,%3}, [%4];" \
        : "=r"((r)[0]), "=r"((r)[1]), "=r"((r)[2]), "=r"((r)[3]) : "r"(a))

#define MMA16816(d, a, b) \
    asm volatile("mma.sync.aligned.m16n8k16.row.col.f32.bf16.bf16.f32 " \
        "{%0,%1,%2,%3}, {%4,%5,%6,%7}, {%8,%9}, {%0,%1,%2,%3};" \
        : "+f"((d)[0]), "+f"((d)[1]), "+f"((d)[2]), "+f"((d)[3]) \
        : "r"((a)[0]), "r"((a)[1]), "r"((a)[2]), "r"((a)[3]), "r"((b)[0]), "r"((b)[1]))

// ---------------- bf16 split ----------------
__device__ __forceinline__ void split_bf16(float v, ushort_t& h, ushort_t& l) {
    __nv_bfloat16 hb = __float2bfloat16(v);
    __nv_bfloat16 lb = __float2bfloat16(v - __bfloat162float(hb));
    h = *reinterpret_cast<ushort_t*>(&hb);
    l = *reinterpret_cast<ushort_t*>(&lb);
}

// ---------------- weight transpose+split: W[K,N] -> Wt[N,K] hi/lo ----------------
__global__ void __launch_bounds__(256) transpose_split(
    const float* __restrict__ W, int K, int N,
    ushort_t* __restrict__ th, ushort_t* __restrict__ tl)
{
    __shared__ float t[32][33];
    int n0 = blockIdx.x * 32, k0 = blockIdx.y * 32;
    int tx = threadIdx.x & 31, ty = threadIdx.x >> 5;
#pragma unroll
    for (int i = 0; i < 32; i += 8)
        t[ty + i][tx] = W[(long)(k0 + ty + i) * N + n0 + tx];
    __syncthreads();
#pragma unroll
    for (int i = 0; i < 32; i += 8) {
        float v = t[tx][ty + i];
        long o = (long)(n0 + ty + i) * K + k0 + tx;
        ushort_t h, l; split_bf16(v, h, l);
        th[o] = h; tl[o] = l;
    }
}

// ---------------- nodes convert ----------------
__global__ void __launch_bounds__(256) conv_split(
    const float* __restrict__ src, ushort_t* __restrict__ dh, ushort_t* __restrict__ dl)
{
    long idx = (long)blockIdx.x * 256 + threadIdx.x;
    float v = src[idx];
    ushort_t h, l; split_bf16(v, h, l);
    dh[idx] = h; dl[idx] = l;
}

// ---------------- combined bias [bq|bk|bv|0|0] ----------------
__global__ void __launch_bounds__(256) bias5_init(
    const float* __restrict__ bq, const float* __restrict__ bk, const float* __restrict__ bv)
{
    int i = blockIdx.x * 256 + threadIdx.x;
    float v = 0.f;
    if (i < 1024)      v = bq[i];
    else if (i < 2048) v = bk[i - 1024];
    else if (i < 3072) v = bv[i - 2048];
    g_bias5[i] = v;
}

// ---------------- HMMA split-bf16 GEMM ----------------
// CTA 128x128, 8 warps of 64x32, K-chunk 64, cp.async double buffer.
// A sources: k < KA -> (a1h,a1l); k >= KA -> (a2h,a2l) at col k-KA,
//            with optional row remap r -> (r/7)*7+6 (gq gather).
#define TILE_B   16384
#define STAGE_B  (4*TILE_B)
#define HMMA_SMEM (2*STAGE_B)   // 131072

__device__ __forceinline__ void load_tile_async(
    unsigned dst, const ushort_t* __restrict__ src, long ld, long r0, int kc, int remap)
{
    int t = threadIdx.x;
    int rr = t >> 3;
    int o  = (t & 7) << 4;
#pragma unroll
    for (int p = 0; p < 4; p++) {
        int r = rr + p * 32;
        long gr = r0 + r;
        if (remap) gr = (gr / 7) * 7 + 6;
        const void* g = (const void*)(src + gr * ld + kc + (o >> 1));
        unsigned s = dst + SMEM_SWIZZLE_128B(r * 128 + o);
        CP_ASYNC16(s, g);
    }
}

__global__ void __launch_bounds__(256) hmma_gemm(
    const ushort_t* __restrict__ a1h, const ushort_t* __restrict__ a1l,
    const ushort_t* __restrict__ a2h, const ushort_t* __restrict__ a2l,
    int KA, int remap2, long lda,
    const ushort_t* __restrict__ b_h, const ushort_t* __restrict__ b_l, long ldb,
    int K,
    const float* __restrict__ bias,
    const float* __restrict__ resid,
    float* __restrict__ C, int ldc,
    ushort_t* __restrict__ o_h, ushort_t* __restrict__ o_l, int ldo,
    int dogelu)
{
    extern __shared__ char smem[];
    unsigned sb = smem_u32(smem);
    const int tid = threadIdx.x;
    const int wid = tid >> 5, lane = tid & 31;
    const int wm = wid & 1, wn = wid >> 1;
    const long row0 = (long)blockIdx.y * 128;
    const int  col0 = blockIdx.x * 128;
    const int NCH = K >> 6;

    float acc[4][4][4];
#pragma unroll
    for (int i = 0; i < 4; i++)
#pragma unroll
        for (int j = 0; j < 4; j++)
#pragma unroll
            for (int e = 0; e < 4; e++) acc[i][j][e] = 0.f;

    const int aRow  = wm * 64 + (lane & 15);
    const int aKoff = (lane >> 4) << 4;
    const int bRow0 = wn * 32 + (lane & 7) + ((lane >> 4) << 3);
    const int bKoff = ((lane >> 3) & 1) << 4;

    // prologue: chunk 0 -> stage 0
    {
        const ushort_t *sh = a1h, *sl = a1l; int kloc = 0, rm = 0;
        if (0 >= KA) { sh = a2h; sl = a2l; kloc = -KA; rm = remap2; }
        load_tile_async(sb + 0 * TILE_B, sh, lda, row0, kloc, rm);
        load_tile_async(sb + 1 * TILE_B, sl, lda, row0, kloc, rm);
        load_tile_async(sb + 2 * TILE_B, b_h, ldb, col0, 0, 0);
        load_tile_async(sb + 3 * TILE_B, b_l, ldb, col0, 0, 0);
        CP_COMMIT();
        CP_WAIT0();
    }
    __syncthreads();

    for (int c = 0; c < NCH; c++) {
        int s = c & 1;
        if (c + 1 < NCH) {
            unsigned sn = sb + (s ^ 1) * STAGE_B;
            int kc = (c + 1) << 6;
            const ushort_t *sh = a1h, *sl = a1l; int kloc = kc, rm = 0;
            if (kc >= KA) { sh = a2h; sl = a2l; kloc = kc - KA; rm = remap2; }
            load_tile_async(sn + 0 * TILE_B, sh, lda, row0, kloc, rm);
            load_tile_async(sn + 1 * TILE_B, sl, lda, row0, kloc, rm);
            load_tile_async(sn + 2 * TILE_B, b_h, ldb, col0, kc, 0);
            load_tile_async(sn + 3 * TILE_B, b_l, ldb, col0, kc, 0);
            CP_COMMIT();
        }
        unsigned stage = sb + s * STAGE_B;
#pragma unroll
        for (int k16 = 0; k16 < 4; k16++) {
            unsigned ah[4][4], al[4][4];
#pragma unroll
            for (int mt = 0; mt < 4; mt++) {
                unsigned off = (unsigned)((aRow + mt * 16) * 128 + k16 * 32 + aKoff);
                off = SMEM_SWIZZLE_128B(off);
                LDSM4(ah[mt], stage + 0 * TILE_B + off);
                LDSM4(al[mt], stage + 1 * TILE_B + off);
            }
            unsigned bhf[4][2], blf[4][2];
#pragma unroll
            for (int np = 0; np < 2; np++) {
                unsigned off = (unsigned)((bRow0 + np * 16) * 128 + k16 * 32 + bKoff);
                off = SMEM_SWIZZLE_128B(off);
                unsigned r[4];
                LDSM4(r, stage + 2 * TILE_B + off);
                bhf[2*np][0] = r[0]; bhf[2*np][1] = r[1];
                bhf[2*np+1][0] = r[2]; bhf[2*np+1][1] = r[3];
                LDSM4(r, stage + 3 * TILE_B + off);
                blf[2*np][0] = r[0]; blf[2*np][1] = r[1];
                blf[2*np+1][0] = r[2]; blf[2*np+1][1] = r[3];
            }
#pragma unroll
            for (int mt = 0; mt < 4; mt++)
#pragma unroll
                for (int nt = 0; nt < 4; nt++) {
                    MMA16816(acc[mt][nt], ah[mt], bhf[nt]);
                    MMA16816(acc[mt][nt], ah[mt], blf[nt]);
                    MMA16816(acc[mt][nt], al[mt], bhf[nt]);
                }
        }
        if (c + 1 < NCH) CP_WAIT0();
        __syncthreads();
    }

    // epilogue
#pragma unroll
    for (int mt = 0; mt < 4; mt++)
#pragma unroll
        for (int h = 0; h < 2; h++) {
            long r = row0 + wm * 64 + mt * 16 + (lane >> 2) + h * 8;
#pragma unroll
            for (int nt = 0; nt < 4; nt++)
#pragma unroll
                for (int e = 0; e < 2; e++) {
                    int col = col0 + wn * 32 + nt * 8 + (lane & 3) * 2 + e;
                    float v = acc[mt][nt][h * 2 + e];
                    if (bias)  v += bias[col];
                    if (resid) v += resid[r * 1024 + col];
                    if (dogelu) v = gelu_f(v);
                    if (C) C[r * (long)ldc + col] = v;
                    if (o_h) {
                        ushort_t hh, ll; split_bf16(v, hh, ll);
                        o_h[r * (long)ldo + col] = hh;
                        o_l[r * (long)ldo + col] = ll;
                    }
                }
        }
}

// ---------------- per-batch attention + edge MLP + softmax + messages ----------------
// qkv layout per row (ld 5120): [q | k | v | la | rb]
__global__ void __launch_bounds__(256) attn_edge_kernel(
    const float* __restrict__ qkv, const float* __restrict__ cc,
    const float* __restrict__ be1, const float* __restrict__ We2, const float* __restrict__ be2,
    float* __restrict__ attn_out,
    ushort_t* __restrict__ mh, ushort_t* __restrict__ ml)
{
    const int b = blockIdx.x;
    const int tid = threadIdx.x;
    const int warp = tid >> 5, lane = tid & 31;
    __shared__ float sRB[7][1024];
    __shared__ float sW2[1024];
    __shared__ float sP[7][7];

    if (tid < 49) sP[tid / 7][tid % 7] = -10000.f;
    for (int idx = tid; idx < 7 * 1024; idx += 256) {
        int m = idx >> 10, d = idx & 1023;
        sRB[m][d] = qkv[((long)b * 7 + m) * 5120 + 4096 + d] + cc[(long)b * 1024 + d] + be1[d];
    }
    for (int d = tid; d < 1024; d += 256) sW2[d] = We2[d];
    __syncthreads();

    for (int p = warp; p < 41; p += 8) {
        int pm = c_pairs[p];
        int n = pm / 7, m = pm % 7;
        const float* qp  = qkv + ((long)b * 7 + n) * 5120;
        const float* kp  = qkv + ((long)b * 7 + m) * 5120 + 1024;
        const float* lap = qkv + ((long)b * 7 + n) * 5120 + 3072;
        float s = 0.f, e = 0.f;
        for (int d = lane; d < 1024; d += 32) {
            s = fmaf(qp[d], kp[d], s);
            float x = lap[d] + sRB[m][d];
            e = fmaf(gelu_f(x), sW2[d], e);
        }
#pragma unroll
        for (int o = 16; o > 0; o >>= 1) {
            s += __shfl_xor_sync(0xffffffffu, s, o);
            e += __shfl_xor_sync(0xffffffffu, e, o);
        }
        if (lane == 0)
            sP[n][m] = s * (1.f / 32.f) + e + be2[0];
    }
    __syncthreads();
    if (tid < 7) {
        int n = tid;
        float mx = -1e30f;
        for (int m = 0; m < 7; m++) mx = fmaxf(mx, sP[n][m]);
        float pv[7], sum = 0.f;
        for (int m = 0; m < 7; m++) { pv[m] = expf(sP[n][m] - mx); sum += pv[m]; }
        float inv = 1.f / sum;
        for (int m = 0; m < 7; m++) {
            float a = pv[m] * inv;
            sP[n][m] = a;
            attn_out[(long)b * 49 + n * 7 + m] = a;
        }
    }
    __syncthreads();
    for (int idx = tid; idx < 7 * 1024; idx += 256) {
        int n = idx >> 10, d = idx & 1023;
        float s = 0.f;
#pragma unroll
        for (int m = 0; m < 7; m++)
            s = fmaf(sP[n][m], qkv[((long)b * 7 + m) * 5120 + 2048 + d], s);
        ushort_t h, l; split_bf16(s, h, l);
        long o = ((long)b * 7 + n) * 1024 + d;
        mh[o] = h; ml[o] = l;
    }
}

// ---------------- importance logits ----------------
__global__ void __launch_bounds__(256) imp_logit_kernel(
    const float* __restrict__ i1, const float* __restrict__ Wi2,
    const float* __restrict__ bi2, float* __restrict__ out)
{
    int row  = blockIdx.x * 8 + (threadIdx.x >> 5);
    int lane = threadIdx.x & 31;
    const float* p = i1 + (long)row * 1024;
    float s = 0.f;
    for (int d = lane; d < 1024; d += 32) s = fmaf(p[d], Wi2[d], s);
#pragma unroll
    for (int o = 16; o > 0; o >>= 1) s += __shfl_xor_sync(0xffffffffu, s, o);
    if (lane == 0) out[row] = s + bi2[0];
}

// ---------------- per-batch finalize ----------------
__global__ void __launch_bounds__(256) finalize_kernel(
    const float* __restrict__ upd, const float* __restrict__ implogit,
    float* __restrict__ out_fused, float* __restrict__ out_imp)
{
    const int b = blockIdx.x;
    const int tid = threadIdx.x;
    const int warp = tid >> 5, lane = tid & 31;
    __shared__ float sU[7][1024];
    __shared__ float sF[1024];
    __shared__ float simp[7];
    __shared__ float sdot[7][7];
    __shared__ float sal[7];
    __shared__ float sff;

    for (int idx = tid; idx < 7 * 1024; idx += 256)
        sU[idx >> 10][idx & 1023] = upd[(long)b * 7168 + idx];

    if (tid == 0) {
        const float capv[7]  = {1.f, 1.f, 1.f, 0.26f, 1.f, 1.f, 0.24f};
        const float freev[7] = {1.f, 1.f, 1.f, 0.f,   1.f, 1.f, 0.f};
        float l[7], mx = -1e30f;
        for (int n = 0; n < 7; n++) { l[n] = implogit[b * 7 + n]; mx = fmaxf(mx, l[n]); }
        float sum = 0.f;
        for (int n = 0; n < 7; n++) { l[n] = expf(l[n] - mx); sum += l[n]; }
        float imp[7];
        for (int n = 0; n < 7; n++) imp[n] = l[n] / sum;
        float capped[7], fm = 0.f, cs = 0.f;
        for (int n = 0; n < 7; n++) {
            capped[n] = fminf(imp[n], capv[n]);
            fm += imp[n] * freev[n];
            cs += capped[n];
        }
        float residual = fmaxf(1.f - cs, 0.f);
        float redis[7], tot = 0.f;
        for (int n = 0; n < 7; n++) {
            float share = (fm > 1e-6f) ? (imp[n] * freev[n] / fmaxf(fm, 1e-6f))
                                       : (freev[n] / 5.f);
            redis[n] = capped[n] + share * residual;
            tot += redis[n];
        }
        float invt = 1.f / fmaxf(tot, 1e-6f);
        for (int n = 0; n < 7; n++) {
            float r = redis[n] * invt;
            simp[n] = r;
            out_imp[b * 7 + n] = r;
        }
    }
    __syncthreads();

    for (int d = tid; d < 1024; d += 256) {
        float f = 0.f;
#pragma unroll
        for (int n = 0; n < 7; n++) f = fmaf(simp[n], sU[n][d], f);
        sF[d] = f;
        out_fused[(long)b * 1024 + d] = f;
    }
    __syncthreads();

    for (int p = warp; p < 36; p += 8) {
        const float *x, *y;
        int n = 0, m = 0;
        if (p < 28) {
            int t = p;
            while (t >= 7 - n) { t -= 7 - n; n++; }
            m = n + t;
            x = sU[n]; y = sU[m];
        } else if (p < 35) {
            n = p - 28; x = sU[n]; y = sF;
        } else {
            x = sF; y = sF;
        }
        float s = 0.f;
        for (int d = lane; d < 1024; d += 32) s = fmaf(x[d], y[d], s);
#pragma unroll
        for (int o = 16; o > 0; o >>= 1) s += __shfl_xor_sync(0xffffffffu, s, o);
        if (lane == 0) {
            if (p < 28)      { sdot[n][m] = s; sdot[m][n] = s; }
            else if (p < 35) { sal[n] = s; }
            else             { sff = s; }
        }
    }
    __syncthreads();

    if (tid == 0) {
        float nrm[7];
        for (int n = 0; n < 7; n++) nrm[n] = sqrtf(sdot[n][n]);
        float nf = sqrtf(sff);
        float edge = 0.f, non = 0.f, al = 0.f;
        for (int n = 0; n < 7; n++) {
            for (int m = 0; m < 7; m++) {
                float cosv = sdot[n][m] / fmaxf(nrm[n] * nrm[m], 1e-8f);
                if (c_adj[n * 7 + m]) edge += 1.f - cosv;
                else                  non  += fmaxf(cosv - 0.35f, 0.f);
            }
            al += 1.f - sal[n] / (fmaxf(nrm[n], 1e-12f) * fmaxf(nf, 1e-12f));
        }
        g_pedge[b] = edge;
        g_pnon[b]  = non;
        g_palign[b] = al;
    }
}

// ---------------- deterministic loss reduction ----------------
__global__ void __launch_bounds__(256) loss_kernel(float* __restrict__ out_phys,
                                                   float* __restrict__ out_align)
{
    __shared__ float se[256], sn[256], sa[256];
    int tid = threadIdx.x;
    float e = 0.f, n = 0.f, a = 0.f;
    for (int b = tid; b < BSZ; b += 256) { e += g_pedge[b]; n += g_pnon[b]; a += g_palign[b]; }
    se[tid] = e; sn[tid] = n; sa[tid] = a;
    __syncthreads();
    for (int o = 128; o > 0; o >>= 1) {
        if (tid < o) { se[tid] += se[tid + o]; sn[tid] += sn[tid + o]; sa[tid] += sa[tid + o]; }
        __syncthreads();
    }
    if (tid == 0) {
        out_phys[0]  = se[0] / 41.f + 0.5f * (sn[0] / 8.f);
        out_align[0] = sa[0] / (1024.f * 7.f);
    }
}

// ---------------- launch ----------------
extern "C" void kernel_launch(void* const* d_in, const int* in_sizes, int n_in,
                              void* d_out, int out_size)
{
    const float* nodes = (const float*)d_in[0];
    const float* Wq  = (const float*)d_in[1];
    const float* bq  = (const float*)d_in[2];
    const float* Wk  = (const float*)d_in[3];
    const float* bk  = (const float*)d_in[4];
    const float* Wv  = (const float*)d_in[5];
    const float* bv  = (const float*)d_in[6];
    const float* We1 = (const float*)d_in[7];
    const float* be1 = (const float*)d_in[8];
    const float* We2 = (const float*)d_in[9];
    const float* be2 = (const float*)d_in[10];
    const float* Wu1 = (const float*)d_in[11];
    const float* bu1 = (const float*)d_in[12];
    const float* Wu2 = (const float*)d_in[13];
    const float* bu2 = (const float*)d_in[14];
    const float* Wi1 = (const float*)d_in[15];
    const float* bi1 = (const float*)d_in[16];
    const float* Wi2 = (const float*)d_in[17];
    const float* bi2 = (const float*)d_in[18];

    float* out = (float*)d_out;
    const long OFF_FUSED = 0;
    const long OFF_UPD   = 1024L * 1024;
    const long OFF_IMP   = OFF_UPD + 7168L * 1024;
    const long OFF_ATTN  = OFF_IMP + 7168;
    const long OFF_PHYS  = OFF_ATTN + 1024L * 49;
    const long OFF_ALIGN = OFF_PHYS + 1;

    float *pqkv, *pcc, *pi1, *pil, *pbias5;
    cudaGetSymbolAddress((void**)&pqkv, g_qkv);
    cudaGetSymbolAddress((void**)&pcc,  g_cc);
    cudaGetSymbolAddress((void**)&pi1,  g_i1);
    cudaGetSymbolAddress((void**)&pil,  g_implogit);
    cudaGetSymbolAddress((void**)&pbias5, g_bias5);

    ushort_t *xh, *xl, *mh, *ml, *uh, *ul, *h1h, *h1l;
    ushort_t *w5h, *w5l, *wch, *wcl, *wu1h, *wu1l, *wu2h, *wu2l, *wi1h, *wi1l;
    cudaGetSymbolAddress((void**)&xh, g_xh);   cudaGetSymbolAddress((void**)&xl, g_xl);
    cudaGetSymbolAddress((void**)&mh, g_mh);   cudaGetSymbolAddress((void**)&ml, g_ml);
    cudaGetSymbolAddress((void**)&uh, g_uh);   cudaGetSymbolAddress((void**)&ul, g_ul);
    cudaGetSymbolAddress((void**)&h1h, g_h1h); cudaGetSymbolAddress((void**)&h1l, g_h1l);
    cudaGetSymbolAddress((void**)&w5h, g_w5h); cudaGetSymbolAddress((void**)&w5l, g_w5l);
    cudaGetSymbolAddress((void**)&wch, g_wch); cudaGetSymbolAddress((void**)&wcl, g_wcl);
    cudaGetSymbolAddress((void**)&wu1h, g_wu1h); cudaGetSymbolAddress((void**)&wu1l, g_wu1l);
    cudaGetSymbolAddress((void**)&wu2h, g_wu2h); cudaGetSymbolAddress((void**)&wu2l, g_wu2l);
    cudaGetSymbolAddress((void**)&wi1h, g_wi1h); cudaGetSymbolAddress((void**)&wi1l, g_wi1l);

    cudaFuncSetAttribute(hmma_gemm, cudaFuncAttributeMaxDynamicSharedMemorySize, HMMA_SMEM);

    dim3 blk(256);
    dim3 gT1(32, 32);
    dim3 gT2(32, 64);
    dim3 gFused(40, 56);   // 5120/128 x 7168/128
    dim3 gBig(8, 56);
    dim3 gCc(8, 8);
    int  convBlocks = (int)((7168L * 1024) / 256);
    const int BIGKA = 1 << 30;

    // weight transposes + splits (into concatenated buffer for q,k,v,la,rb)
    transpose_split<<<gT1, blk>>>(Wq, 1024, 1024, w5h + 0L * 1024 * 1024, w5l + 0L * 1024 * 1024);
    transpose_split<<<gT1, blk>>>(Wk, 1024, 1024, w5h + 1L * 1024 * 1024, w5l + 1L * 1024 * 1024);
    transpose_split<<<gT1, blk>>>(Wv, 1024, 1024, w5h + 2L * 1024 * 1024, w5l + 2L * 1024 * 1024);
    transpose_split<<<gT1, blk>>>(We1,               1024, 1024, w5h + 3L * 1024 * 1024, w5l + 3L * 1024 * 1024);
    transpose_split<<<gT1, blk>>>(We1 + 1024 * 1024, 1024, 1024, w5h + 4L * 1024 * 1024, w5l + 4L * 1024 * 1024);
    transpose_split<<<gT1, blk>>>(We1 + 2 * 1024 * 1024, 1024, 1024, wch, wcl);
    transpose_split<<<gT2, blk>>>(Wu1, 2048, 1024, wu1h, wu1l);
    transpose_split<<<gT1, blk>>>(Wu2, 1024, 1024, wu2h, wu2l);
    transpose_split<<<gT2, blk>>>(Wi1, 2048, 1024, wi1h, wi1l);
    bias5_init<<<20, blk>>>(bq, bk, bv);

    // nodes -> split
    conv_split<<<convBlocks, blk>>>(nodes, xh, xl);

    // fused [q|k|v|la|rb] = nodes @ [Wq|Wk|Wv|Wa|Wb], N=5120
    hmma_gemm<<<gFused, blk, HMMA_SMEM>>>(xh, xl, nullptr, nullptr, BIGKA, 0, 1024,
                                          w5h, w5l, 1024, 1024,
                                          pbias5, nullptr, pqkv, 5120,
                                          nullptr, nullptr, 0, 0);
    // cc = nodes[:, -1] @ Wc  (A rows stride 7*1024, offset 6*1024)
    hmma_gemm<<<gCc, blk, HMMA_SMEM>>>(xh + 6 * 1024, xl + 6 * 1024, nullptr, nullptr, BIGKA, 0, 7 * 1024,
                                       wch, wcl, 1024, 1024,
                                       nullptr, nullptr, pcc, 1024,
                                       nullptr, nullptr, 0, 0);

    attn_edge_kernel<<<1024, blk>>>(pqkv, pcc, be1, We2, be2, out + OFF_ATTN, mh, ml);

    // h1 = gelu([nodes|msg] @ Wu1 + bu1) -> bf16 split only
    hmma_gemm<<<gBig, blk, HMMA_SMEM>>>(xh, xl, mh, ml, 1024, 0, 1024,
                                        wu1h, wu1l, 2048, 2048,
                                        bu1, nullptr, nullptr, 0,
                                        h1h, h1l, 1024, 1);
    // updated = h1 @ Wu2 + bu2 + nodes -> fp32 out + bf16 split
    hmma_gemm<<<gBig, blk, HMMA_SMEM>>>(h1h, h1l, nullptr, nullptr, BIGKA, 0, 1024,
                                        wu2h, wu2l, 1024, 1024,
                                        bu2, nodes, out + OFF_UPD, 1024,
                                        uh, ul, 1024, 0);
    // i1 = gelu([updated|gq] @ Wi1 + bi1); gq via row remap on second K half
    hmma_gemm<<<gBig, blk, HMMA_SMEM>>>(uh, ul, uh, ul, 1024, 1, 1024,
                                        wi1h, wi1l, 2048, 2048,
                                        bi1, nullptr, pi1, 1024,
                                        nullptr, nullptr, 0, 1);

    imp_logit_kernel<<<896, blk>>>(pi1, Wi2, bi2, pil);
    finalize_kernel<<<1024, blk>>>(out + OFF_UPD, pil, out + OFF_FUSED, out + OFF_IMP);
    loss_kernel<<<1, blk>>>(out + OFF_PHYS, out + OFF_ALIGN);
}